// round 3
// baseline (speedup 1.0000x reference)
#include <cuda_runtime.h>

// GeneratorCell: B=128, M=32 queue rows, N=64 strokes, K=2048 stroke length
#define Bn 128
#define Mn 32
#define Nn 64
#define Kn 2048
#define NT 704                     // 22 warps
#define Cn 3                       // consecutive p's per thread; 704*3 = 2112 = N + M*N
#define PAD 64
#define EMB_SZ (PAD + Kn + PAD)    // zero-padded emb => branch-free inner loop

typedef unsigned long long ull;

__device__ __forceinline__ float sigmoidf_(float x) { return 1.0f / (1.0f + __expf(-x)); }

__device__ __forceinline__ ull pack2(float x, float y) {
    ull r; asm("mov.b64 %0, {%1,%2};" : "=l"(r) : "f"(x), "f"(y)); return r;
}
__device__ __forceinline__ void unpack2(ull v, float& x, float& y) {
    asm("mov.b64 {%0,%1}, %2;" : "=f"(x), "=f"(y) : "l"(v));
}
// packed f32x2 FMA (sm_100+): d = a*b + c per 32-bit lane
__device__ __forceinline__ ull ffma2(ull a, ull b, ull c) {
    ull d; asm("fma.rn.f32x2 %0, %1, %2, %3;" : "=l"(d) : "l"(a), "l"(b), "l"(c)); return d;
}

__global__ __launch_bounds__(NT) void gen_cell_kernel(
    const float* __restrict__ qt1,      // [B, M, N, 2]
    const float* __restrict__ ht1,      // [B, N, 2]
    const float* __restrict__ zt,       // [B, N]
    const float* __restrict__ alpha_t,  // [B, N]
    const float* __restrict__ conv_w,   // [2, 2, M+1, 1]
    const float* __restrict__ conv_b,   // [2]
    const float* __restrict__ W_xr, const float* __restrict__ W_hr, const float* __restrict__ b_r,
    const float* __restrict__ W_xu, const float* __restrict__ W_hu, const float* __restrict__ b_u,
    const float* __restrict__ W_xn, const float* __restrict__ W_hn, const float* __restrict__ b_n,
    const float* __restrict__ lin_w,    // [N, 2N]
    const float* __restrict__ lin_b,    // [N]
    const float* __restrict__ W_emb,    // [K, 2]
    float* __restrict__ out)            // st [B,N,2] | qt [B,M,N,2] | ht [B,N,2]
{
    __shared__ float s_ex[EMB_SZ];      // emb channel x, zero-padded
    __shared__ float s_ey[EMB_SZ];      // emb channel y, zero-padded
    __shared__ ull   s_coef2[Nn];       // (coef, coef) packed f32x2
    __shared__ float s_ht[2 * Nn];

    const int b   = blockIdx.x;
    const int tid = threadIdx.x;
    const float*  q  = qt1 + (size_t)b * Mn * Nn * 2;
    const float2* qf = (const float2*)q;

    if (tid >= 64) {
        // ---- staging crew (640 threads): W_emb -> SoA shared + zero pads ----
        const int t2 = tid - 64;
        if (t2 < PAD) {
            s_ex[t2] = 0.0f; s_ey[t2] = 0.0f;
            s_ex[PAD + Kn + t2] = 0.0f; s_ey[PAD + Kn + t2] = 0.0f;
        }
        const float4* we4 = (const float4*)W_emb;   // 2 emb entries per float4
        for (int i = t2; i < Kn / 2; i += (NT - 64)) {
            float4 w = we4[i];
            s_ex[PAD + 2 * i]     = w.x; s_ey[PAD + 2 * i]     = w.y;
            s_ex[PAD + 2 * i + 1] = w.z; s_ey[PAD + 2 * i + 1] = w.w;
        }
    } else {
        // ---- phase 1 (threads 0..63): (M+1)-tap conv + GRU per stroke n ----
        // dual accumulators per output channel to break the FMA dependency chain
        const int n = tid;
        float h0a = conv_b[0], h0b = 0.0f, h1a = conv_b[1], h1b = 0.0f;
        #pragma unroll 8
        for (int h = 0; h < Mn; h += 2) {
            float2 va = qf[h * Nn + n];
            float2 vb = qf[(h + 1) * Nn + n];
            h0a = fmaf(va.x, conv_w[h],          fmaf(va.y, conv_w[33 + h],     h0a));
            h1a = fmaf(va.x, conv_w[66 + h],     fmaf(va.y, conv_w[99 + h],     h1a));
            h0b = fmaf(vb.x, conv_w[h + 1],      fmaf(vb.y, conv_w[33 + h + 1], h0b));
            h1b = fmaf(vb.x, conv_w[66 + h + 1], fmaf(vb.y, conv_w[99 + h + 1], h1b));
        }
        const float2 hv = ((const float2*)ht1)[b * Nn + n];
        float h0 = h0a + h0b + hv.x * conv_w[32] + hv.y * conv_w[65];
        float h1 = h1a + h1b + hv.x * conv_w[98] + hv.y * conv_w[131];

        const float x0 = zt[b * Nn + n];
        const float x1 = alpha_t[b * Nn + n];

        float r0 = sigmoidf_(fmaf(x0, W_xr[0], fmaf(x1, W_xr[2], fmaf(h0, W_hr[0], fmaf(h1, W_hr[2], b_r[0])))));
        float r1 = sigmoidf_(fmaf(x0, W_xr[1], fmaf(x1, W_xr[3], fmaf(h0, W_hr[1], fmaf(h1, W_hr[3], b_r[1])))));
        float u0 = sigmoidf_(fmaf(x0, W_xu[0], fmaf(x1, W_xu[2], fmaf(h0, W_hu[0], fmaf(h1, W_hu[2], b_u[0])))));
        float u1 = sigmoidf_(fmaf(x0, W_xu[1], fmaf(x1, W_xu[3], fmaf(h0, W_hu[1], fmaf(h1, W_hu[3], b_u[1])))));

        const float rh0 = r0 * h0, rh1 = r1 * h1;
        float nt0 = tanhf(fmaf(x0, W_xn[0], fmaf(x1, W_xn[2], fmaf(rh0, W_hn[0], fmaf(rh1, W_hn[2], b_n[0])))));
        float nt1 = tanhf(fmaf(x0, W_xn[1], fmaf(x1, W_xn[3], fmaf(rh0, W_hn[1], fmaf(rh1, W_hn[3], b_n[1])))));

        const float hn0 = u0 * hv.x + (1.0f - u0) * nt0;
        const float hn1 = u1 * hv.y + (1.0f - u1) * nt1;

        s_ht[2 * n + 0] = hn0;
        s_ht[2 * n + 1] = hn1;

        const size_t off_ht = (size_t)Bn * Nn * 2 + (size_t)Bn * Mn * Nn * 2;
        out[off_ht + ((size_t)b * Nn + n) * 2 + 0] = hn0;
        out[off_ht + ((size_t)b * Nn + n) * 2 + 1] = hn1;
    }
    __syncthreads();

    // ---- phase 2 (threads 0..63): it[n] = ht_flat . lin_w[n] + lin_b[n]; coef = it*alpha ----
    if (tid < 64) {
        const int n = tid;
        // 4-way split accumulation to break the 128-FMA serial chain
        float a0 = lin_b[n], a1 = 0.0f, a2 = 0.0f, a3 = 0.0f;
        const float* lw = lin_w + (size_t)n * 2 * Nn;
        #pragma unroll 8
        for (int j = 0; j < 2 * Nn; j += 4) {
            a0 = fmaf(s_ht[j + 0], lw[j + 0], a0);
            a1 = fmaf(s_ht[j + 1], lw[j + 1], a1);
            a2 = fmaf(s_ht[j + 2], lw[j + 2], a2);
            a3 = fmaf(s_ht[j + 3], lw[j + 3], a3);
        }
        const float c = ((a0 + a1) + (a2 + a3)) * alpha_t[b * Nn + n];
        s_coef2[n] = pack2(c, c);
    }
    __syncthreads();

    // ---- phase 3: FIR overlap-add, per-thread sliding window over 3 consecutive p ----
    const int p0 = tid * Cn;
    ull acc0 = 0, acc1 = 0, acc2 = 0;
    ull w0 = pack2(s_ex[PAD + p0 + 0], s_ey[PAD + p0 + 0]);
    ull w1 = pack2(s_ex[PAD + p0 + 1], s_ey[PAD + p0 + 1]);
    ull w2 = pack2(s_ex[PAD + p0 + 2], s_ey[PAD + p0 + 2]);
    #pragma unroll
    for (int n = 0; n < Nn; n++) {
        const ull c2 = s_coef2[n];                 // warp-uniform broadcast
        acc0 = ffma2(c2, w0, acc0);
        acc1 = ffma2(c2, w1, acc1);
        acc2 = ffma2(c2, w2, acc2);
        // slide window: fully unrolled loop => pure register renaming
        w2 = w1; w1 = w0;
        w0 = pack2(s_ex[PAD + p0 - n - 1], s_ey[PAD + p0 - n - 1]);  // stride 3: conflict-free
    }

    // ---- output assembly ----
    float2* st_out = (float2*)out + (size_t)b * Nn;
    float2* qt_out = (float2*)(out + (size_t)Bn * Nn * 2) + (size_t)b * Mn * Nn;
    ull accs[Cn] = {acc0, acc1, acc2};
    #pragma unroll
    for (int i = 0; i < Cn; i++) {
        const int p = p0 + i;
        float fx, fy; unpack2(accs[i], fx, fy);
        float2 qv = make_float2(0.0f, 0.0f);
        if (p < Mn * Nn) qv = qf[p];               // q_shift[j] = q_flat[j+N] = q_flat[p]
        float2 r = make_float2(qv.x + fx, qv.y + fy);
        if (p < Nn) st_out[p] = r;                 // st = q_row0 + f[:N]
        else        qt_out[p - Nn] = r;            // qt = q_shift + tail
    }
}

extern "C" void kernel_launch(void* const* d_in, const int* in_sizes, int n_in,
                              void* d_out, int out_size) {
    const float* qt1     = (const float*)d_in[0];
    const float* ht1     = (const float*)d_in[1];
    const float* zt      = (const float*)d_in[2];
    const float* alpha_t = (const float*)d_in[3];
    const float* conv_w  = (const float*)d_in[4];
    const float* conv_b  = (const float*)d_in[5];
    const float* W_xr    = (const float*)d_in[6];
    const float* W_hr    = (const float*)d_in[7];
    const float* b_r     = (const float*)d_in[8];
    const float* W_xu    = (const float*)d_in[9];
    const float* W_hu    = (const float*)d_in[10];
    const float* b_u     = (const float*)d_in[11];
    const float* W_xn    = (const float*)d_in[12];
    const float* W_hn    = (const float*)d_in[13];
    const float* b_n     = (const float*)d_in[14];
    const float* lin_w   = (const float*)d_in[15];
    const float* lin_b   = (const float*)d_in[16];
    const float* W_emb   = (const float*)d_in[17];

    gen_cell_kernel<<<Bn, NT>>>(qt1, ht1, zt, alpha_t, conv_w, conv_b,
                                W_xr, W_hr, b_r, W_xu, W_hu, b_u,
                                W_xn, W_hn, b_n, lin_w, lin_b, W_emb,
                                (float*)d_out);
}